// round 5
// baseline (speedup 1.0000x reference)
#include <cuda_runtime.h>
#include <math_constants.h>

// SoftDTW-variant, gamma = 1.0, B = 32, T = 512.
// NOTE the reference semantics: cost of cell (i,j) is ds[i] = (x[i]-y[i])^2,
// broadcast along the row (elementwise diff, NOT pairwise).
//
// R[i][j] = ds[i-1] + softmin(R[i-1][j], R[i][j-1], R[i-1][j-1])
// R[0][0]=0, R[0][j>0]=inf, R[i>0][0]=inf.  Output = mean_b R[T][T].
//
// One CTA per batch; anti-diagonal wavefront, one thread per column, three
// rotating shared diagonal buffers, one __syncthreads per diagonal.

#define TLEN 512
#define BATCH 32

__device__ float g_partial[BATCH];

__global__ __launch_bounds__(TLEN) void softdtw_kernel(const float* __restrict__ x,
                                                       const float* __restrict__ y) {
    __shared__ float ds[TLEN];              // row costs: (x[i]-y[i])^2
    __shared__ float buf[3][TLEN + 1];

    const int b   = blockIdx.x;
    const int tid = threadIdx.x;
    const int j   = tid + 1;                // column index 1..T

    {
        const float xv = x[b * TLEN + tid];
        const float yv = y[b * TLEN + tid];
        const float df = xv - yv;
        ds[tid] = df * df;
    }

    // Initialize all three diagonal buffers to +inf.
    // Boundary invariants (proved in R1 analysis):
    //  - entry [0] of the current buffer is re-set to inf every diagonal
    //  - entry j of buffer (j mod 3) is first written as a cell only at
    //    diagonal >= j+1, so the row-0 inf survives until it is consumed.
    for (int k = tid; k < 3 * (TLEN + 1); k += TLEN) {
        (&buf[0][0])[k] = CUDART_INF_F;
    }
    __syncthreads();
    if (tid == 0) buf[0][0] = 0.0f;         // R[0][0] on diagonal d=0 (buf 0)
    __syncthreads();

    for (int d = 2; d <= 2 * TLEN; ++d) {
        float*       cur = buf[d % 3];
        const float* p1  = buf[(d - 1) % 3];    // diagonal d-1
        const float* p2  = buf[(d + 1) % 3];    // diagonal d-2 ((d-2)%3==(d+1)%3)

        if (j <= d - 1 && j >= d - TLEN) {
            const int   i    = d - j;           // row 1..T
            const float dd   = ds[i - 1];       // row-broadcast cost

            const float up   = p1[j];           // R[i-1][j]
            const float left = p1[j - 1];       // R[i][j-1]
            const float dg   = p2[j - 1];       // R[i-1][j-1]

            // softmin pivoted at the (always finite) min: sum in [1,3];
            // __expf(-inf) = 0 handles inf boundaries exactly.
            const float m = fminf(fminf(up, left), dg);
            const float s = __expf(m - up) + __expf(m - left) + __expf(m - dg);
            cur[j] = dd + m - __logf(s);
        }
        if (tid == 0) cur[0] = CUDART_INF_F;    // column-0 boundary
        __syncthreads();
    }

    if (tid == TLEN - 1) {
        g_partial[b] = buf[(2 * TLEN) % 3][TLEN];   // R[T][T]
    }
}

__global__ void reduce_kernel(float* __restrict__ out) {
    float s = 0.0f;
#pragma unroll
    for (int i = 0; i < BATCH; ++i) s += g_partial[i];
    out[0] = s * (1.0f / BATCH);
}

extern "C" void kernel_launch(void* const* d_in, const int* in_sizes, int n_in,
                              void* d_out, int out_size) {
    const float* x = (const float*)d_in[0];
    const float* y = (const float*)d_in[1];
    softdtw_kernel<<<BATCH, TLEN>>>(x, y);
    reduce_kernel<<<1, 1>>>((float*)d_out);
}

// round 6
// speedup vs baseline: 2.9217x; 2.9217x over previous
#include <cuda_runtime.h>

// SoftDTW-variant, gamma=1, B=32, T=512. Cost of cell (i,j) is
// ds[i] = (x[i]-y[i])^2 broadcast along the row.
//
// (A,S)-pair formulation in log2 domain: v = A - log2(S), with
//   m     = min(A_up, A_dg, A_left)
//   S_new = 2^(m-A_up)*S_up + 2^(m-A_dg)*S_dg + 2^(m-A_left)*S_left
//   A_new = m + dd2[i-1]
// LG2 is off the recurrence loop (only renorm every 16 steps + final readout).
//
// 128 threads/CTA (1 warp per SMSP), 4 columns per thread, skewed row-per-step
// wavefront: thread q computes row i = s - q, 639 steps. Intra-warp handoff via
// shfl_up; warp boundaries via a 4-deep smem ring + one __syncthreads per step.

#define TLEN  512
#define BATCH 32
#define NTH   128
#define NSTEP (TLEN + NTH - 1)   // 639
#define BIGV  1e30f              // +inf representation (1e30 + small == 1e30 in fp32)

__device__ __forceinline__ float ex2(float t) {
    float r; asm("ex2.approx.ftz.f32 %0, %1;" : "=f"(r) : "f"(t)); return r;
}
__device__ __forceinline__ float lg2(float t) {
    float r; asm("lg2.approx.f32 %0, %1;" : "=f"(r) : "f"(t)); return r;
}

__global__ __launch_bounds__(NTH) void softdtw_kernel(const float* __restrict__ x,
                                                      const float* __restrict__ y,
                                                      float* __restrict__ out) {
    __shared__ float  dd2[TLEN];     // row costs * log2(e)
    __shared__ float2 bnd[3][4];     // warp-boundary (A,S) ring, indexed [writer warp][step&3]

    const int q    = threadIdx.x;
    const int lane = q & 31;
    const int warp = q >> 5;
    const int b    = blockIdx.x;

    const float L2E = 1.4426950408889634f;
    float4 xv = ((const float4*)(x + b * TLEN))[q];
    float4 yv = ((const float4*)(y + b * TLEN))[q];
    float d0 = xv.x - yv.x, d1 = xv.y - yv.y, d2 = xv.z - yv.z, d3 = xv.w - yv.w;
    ((float4*)dd2)[q] = make_float4(d0*d0*L2E, d1*d1*L2E, d2*d2*L2E, d3*d3*L2E);
    if (q < 12) ((float2*)bnd)[q] = make_float2(BIGV, 1.0f);
    __syncthreads();

    // up-carries for this thread's 4 columns: (A,S) of row i-1. Init = boundary inf.
    float Au0 = BIGV, Au1 = BIGV, Au2 = BIGV, Au3 = BIGV;
    float Su0 = 1.f,  Su1 = 1.f,  Su2 = 1.f,  Su3 = 1.f;
    // dg for cell 0 = neighbor's row i-2... i.e. previous step's left value.
    // Thread 0's first dg is R[0][0] = 0 -> (A=0, S=1); inf otherwise.
    float dgA = (q == 0) ? 0.0f : BIGV;
    float dgS = 1.0f;

    for (int s = 1; s <= NSTEP; ++s) {
        // left neighbor's newest boundary value (its row i = s - q, committed at step s-1)
        float lA = __shfl_up_sync(0xffffffffu, Au3, 1);
        float lS = __shfl_up_sync(0xffffffffu, Su3, 1);
        if (lane == 0) {
            if (warp == 0) { lA = BIGV; lS = 1.0f; }          // column-0 boundary
            else { float2 v = bnd[warp - 1][(s - 1) & 3]; lA = v.x; lS = v.y; }
        }

        const int i  = s - q;                    // this thread's row this step
        int idx = i - 1;
        idx = idx < 0 ? 0 : (idx > TLEN - 1 ? TLEN - 1 : idx);
        const float dd = dd2[idx];               // same for all 4 cells (row-broadcast)

        // cell 0: up=(Au0,Su0)  dg=(dgA,dgS)  left=(lA,lS)
        float m0 = fminf(fminf(Au0, dgA), lA);
        float s0 = ex2(m0 - Au0) * Su0 + ex2(m0 - dgA) * dgS + ex2(m0 - lA) * lS;
        float a0 = m0 + dd;
        // cell 1: dg = old up0
        float m1 = fminf(fminf(Au1, Au0), a0);
        float s1 = ex2(m1 - Au1) * Su1 + ex2(m1 - Au0) * Su0 + ex2(m1 - a0) * s0;
        float a1 = m1 + dd;
        // cell 2: dg = old up1
        float m2 = fminf(fminf(Au2, Au1), a1);
        float s2 = ex2(m2 - Au2) * Su2 + ex2(m2 - Au1) * Su1 + ex2(m2 - a1) * s1;
        float a2 = m2 + dd;
        // cell 3: dg = old up2
        float m3 = fminf(fminf(Au3, Au2), a2);
        float s3 = ex2(m3 - Au3) * Su3 + ex2(m3 - Au2) * Su2 + ex2(m3 - a2) * s2;
        float a3 = m3 + dd;

        // Commit only for valid rows; invalid steps keep carries = inf-rep / frozen.
        if ((unsigned)(i - 1) < (unsigned)TLEN) {
            Au0 = a0; Su0 = s0;  Au1 = a1; Su1 = s1;
            Au2 = a2; Su2 = s2;  Au3 = a3; Su3 = s3;
        }
        dgA = lA; dgS = lS;                       // this step's left becomes next step's dg

        // Renormalize every 16 steps: value A - log2(S) is invariant; keeps S in range.
        if ((s & 15) == 0) {
            Au0 -= lg2(Su0); Su0 = 1.0f;
            Au1 -= lg2(Su1); Su1 = 1.0f;
            Au2 -= lg2(Su2); Su2 = 1.0f;
            Au3 -= lg2(Su3); Su3 = 1.0f;
        }

        // Publish boundary (A,S) for the next warp.
        if (lane == 31 && warp < 3) bnd[warp][s & 3] = make_float2(Au3, Su3);
        __syncthreads();
    }

    if (q == NTH - 1) {
        // v = scaled R[T][T]; unscale by ln2. Mean over batches via atomic.
        float v = (Au3 - lg2(Su3)) * 0.6931471805599453f;
        atomicAdd(out, v * (1.0f / BATCH));
    }
}

extern "C" void kernel_launch(void* const* d_in, const int* in_sizes, int n_in,
                              void* d_out, int out_size) {
    const float* x = (const float*)d_in[0];
    const float* y = (const float*)d_in[1];
    cudaMemsetAsync(d_out, 0, sizeof(float));
    softdtw_kernel<<<BATCH, NTH>>>(x, y, (float*)d_out);
}

// round 8
// speedup vs baseline: 3.0756x; 1.0527x over previous
#include <cuda_runtime.h>

// SoftDTW-variant, gamma=1, B=32, T=512, row-broadcast cost ds[i]=(x[i]-y[i])^2.
// Linear-weight domain: W(i,j) = 2^(P(i) - R(i,j)*log2e), P(i)=sum_{r<=i} ds'[r].
//   W(i,j) = W(i-1,j) + W(i-1,j-1) + c_i * W(i,j-1),  c_i = 2^(-ds'[i])
// Per-thread integer frame exponent k. NUMERIC SAFETY:
//  - pre-tile joint renorm: shift frame so all tile inputs <= 2 -> tile values
//    bounded by ~2^14, inf impossible.
//  - all power-of-2 factors built from bits, two-stage (|shift|<=252 exact,
//    larger flushes to 0 = negligible branch, correct).
//  - post-tile renorm exponent clamped to [-126,126].
//  - all state commits guarded by the active window.
// 128 threads, 4 cols/thread, 4 rows/superstep, shfl intra-warp handoff,
// release/acquire smem ring inter-warp. No block barrier in the loop.

#define TLEN  512
#define BATCH 32
#define NTH   128
#define WSUP  159          // supersteps per warp = 512/4 + 31
#define SENT  0x7fffffff

__device__ __forceinline__ float pow2i(int e) {   // e in [-126,126]
    return __int_as_float((e + 127) << 23);
}
// v * 2^h for h in [-252, 252]; intermediates cannot overflow for our inputs
// (first factor's positive part never exceeds what restores true magnitude).
__device__ __forceinline__ float scale2(float v, int h) {
    int h1 = h < -126 ? -126 : (h > 126 ? 126 : h);
    int h2 = h - h1;
    h2 = h2 < -126 ? -126 : (h2 > 126 ? 126 : h2);
    return v * pow2i(h1) * pow2i(h2);
}

__global__ __launch_bounds__(NTH) void softdtw_kernel(const float* __restrict__ x,
                                                      const float* __restrict__ y,
                                                      float* __restrict__ out) {
    __shared__ float cs[TLEN];          // c_i = 2^{-ds'[i]}
    __shared__ float redsum[4];
    __shared__ int   ring[3][256][8];   // [boundary][slot][0..3 W raw, 4 = k tag/flag]

    const int q    = threadIdx.x;
    const int lane = q & 31;
    const int w    = q >> 5;
    const int b    = blockIdx.x;

    // ---- prologue -----------------------------------------------------------
    const float L2E = 1.4426950408889634f;
    float4 xv = ((const float4*)(x + b * TLEN))[q];
    float4 yv = ((const float4*)(y + b * TLEN))[q];
    float e0 = (xv.x - yv.x) * (xv.x - yv.x) * L2E;
    float e1 = (xv.y - yv.y) * (xv.y - yv.y) * L2E;
    float e2 = (xv.z - yv.z) * (xv.z - yv.z) * L2E;
    float e3 = (xv.w - yv.w) * (xv.w - yv.w) * L2E;
    cs[4*q + 0] = exp2f(-e0);
    cs[4*q + 1] = exp2f(-e1);
    cs[4*q + 2] = exp2f(-e2);
    cs[4*q + 3] = exp2f(-e3);
    float mysum = (e0 + e1) + (e2 + e3);
    #pragma unroll
    for (int o = 16; o; o >>= 1) mysum += __shfl_xor_sync(0xffffffffu, mysum, o);
    if (lane == 0) redsum[w] = mysum;
    for (int s = q; s < 3 * 256; s += NTH) ring[s >> 8][s & 255][4] = SENT;
    __syncthreads();
    const float P = (redsum[0] + redsum[1]) + (redsum[2] + redsum[3]);

    // ---- state --------------------------------------------------------------
    float u0 = 0.f, u1 = 0.f, u2 = 0.f, u3 = 0.f;     // up-carries, frame k
    float nb0 = 0.f, nb1 = 0.f, nb2 = 0.f, nb3 = 0.f; // published boundary, frame kold
    float dgW = (q == 0) ? 1.0f : 0.0f;               // diag input for next row0
    int   k = 0, kold = 0;

    const int t0 = w << 5;
    for (int ts = 0; ts < WSUP; ++ts) {
        const int t = t0 + ts;

        // ---- receive left boundary (4 rows) + producer frame ----
        float l0 = __shfl_up_sync(0xffffffffu, nb0, 1);
        float l1 = __shfl_up_sync(0xffffffffu, nb1, 1);
        float l2 = __shfl_up_sync(0xffffffffu, nb2, 1);
        float l3 = __shfl_up_sync(0xffffffffu, nb3, 1);
        int   kp = __shfl_up_sync(0xffffffffu, kold, 1);

        if (w > 0 && ts <= 127) {
            unsigned fa = (unsigned)__cvta_generic_to_shared(&ring[w - 1][t - 1][4]);
            int kv;
            do {
                asm volatile("ld.acquire.cta.shared.b32 %0, [%1];" : "=r"(kv) : "r"(fa) : "memory");
            } while (kv == SENT);
            if (lane == 0) {
                kp = kv;
                l0 = __int_as_float(ring[w - 1][t - 1][0]);
                l1 = __int_as_float(ring[w - 1][t - 1][1]);
                l2 = __int_as_float(ring[w - 1][t - 1][2]);
                l3 = __int_as_float(ring[w - 1][t - 1][3]);
            }
        } else if (lane == 0) {
            l0 = l1 = l2 = l3 = 0.0f; kp = k;          // col-0 boundary / inactive
        }

        const bool act = (unsigned)(ts - lane) < 128u;

        // ---- pre-tile joint renorm: bring all inputs to <= 2 ----
        const int   dk  = kp - k;
        const float mlx = fmaxf(fmaxf(l0, l1), fmaxf(l2, l3));
        const int   el  = ((__float_as_int(mlx) >> 23) - 127) + dk;  // true exp of max l in my frame
        const int   s   = el > 0 ? el : 0;
        const int   kt  = k + s;                        // tile frame
        const int   hl  = dk - s;                       // l shift into tile frame (<= 0 rel to true)
        l0 = scale2(l0, hl); l1 = scale2(l1, hl);
        l2 = scale2(l2, hl); l3 = scale2(l3, hl);
        int s1c = s > 126 ? 126 : s;
        int s2c = s - s1c; s2c = s2c > 126 ? 126 : s2c;
        const float uf = pow2i(-s1c) * pow2i(-s2c);
        const float v0 = u0 * uf, v1 = u1 * uf, v2 = u2 * uf, v3 = u3 * uf;
        const float dgv = dgW * uf;

        // ---- row costs for this superstep's 4 rows ----
        int ridx = ts - lane;
        ridx = ridx < 0 ? 0 : (ridx > 127 ? 127 : ridx);
        const float4 c4 = *(const float4*)&cs[4 * ridx];

        // ---- 16 cells: W = (up + dg) + c * left ----
        float n0 = fmaf(c4.x, l0, v0 + dgv);
        float n1 = fmaf(c4.x, n0, v1 + v0);
        float n2 = fmaf(c4.x, n1, v2 + v1);
        float n3 = fmaf(c4.x, n2, v3 + v2);
        float m0 = fmaf(c4.y, l1, n0 + l0);
        float m1 = fmaf(c4.y, m0, n1 + n0);
        float m2 = fmaf(c4.y, m1, n2 + n1);
        float m3 = fmaf(c4.y, m2, n3 + n2);
        float p0 = fmaf(c4.z, l2, m0 + l1);
        float p1 = fmaf(c4.z, p0, m1 + m0);
        float p2 = fmaf(c4.z, p1, m2 + m1);
        float p3 = fmaf(c4.z, p2, m3 + m2);
        float o0 = fmaf(c4.w, l3, p0 + l2);
        float o1 = fmaf(c4.w, o0, p1 + p0);
        float o2 = fmaf(c4.w, o1, p2 + p1);
        float o3 = fmaf(c4.w, o2, p3 + p2);

        // ---- post-tile renorm (bounded: mx <= ~2^14) ----
        const float mx = fmaxf(fmaxf(o0, o1), fmaxf(o2, o3));
        int e = (__float_as_int(mx) >> 23) - 127;
        e = e < -126 ? -126 : (e > 126 ? 126 : e);
        if (mx == 0.0f) e = 0;
        const float g = pow2i(-e);

        // ---- commit (active window only) ----
        if (act) {
            u0 = o0 * g; u1 = o1 * g; u2 = o2 * g; u3 = o3 * g;
            dgW = l3 * g;
            k = kt + e;
            nb0 = n3; nb1 = m3; nb2 = p3; nb3 = o3;   // tile frame kt
            kold = kt;
        }

        if (lane == 31 && w < 3) {
            ring[w][t][0] = __float_as_int(nb0);
            ring[w][t][1] = __float_as_int(nb1);
            ring[w][t][2] = __float_as_int(nb2);
            ring[w][t][3] = __float_as_int(nb3);
            unsigned fa = (unsigned)__cvta_generic_to_shared(&ring[w][t][4]);
            asm volatile("st.release.cta.shared.b32 [%0], %1;" :: "r"(fa), "r"(kold) : "memory");
        }
    }

    if (q == NTH - 1) {
        // R(T,T)*log2e = P - k - log2(W_raw); unscale by ln2; mean over batches.
        float Rl2 = P - (float)k - __log2f(u3);
        atomicAdd(out, Rl2 * 0.6931471805599453f * (1.0f / BATCH));
    }
}

extern "C" void kernel_launch(void* const* d_in, const int* in_sizes, int n_in,
                              void* d_out, int out_size) {
    const float* x = (const float*)d_in[0];
    const float* y = (const float*)d_in[1];
    cudaMemsetAsync(d_out, 0, sizeof(float));
    softdtw_kernel<<<BATCH, NTH>>>(x, y, (float*)d_out);
}

// round 10
// speedup vs baseline: 3.6854x; 1.1982x over previous
#include <cuda_runtime.h>

// SoftDTW-variant, gamma=1, B=32, T=512, row-broadcast cost ds[i]=(x[i]-y[i])^2.
// Linear-weight domain: W(i,j) = 2^(P(i) - R(i,j)*log2e), P(i)=sum_{r<=i} ds'[r].
//   W(i,j) = W(i-1,j) + W(i-1,j-1) + c_i * W(i,j-1),  c_i = 2^(-ds'[i])
// 2 fp ops/cell, no MUFU in the loop. Boundaries (R=inf) are W=0.
// Numeric safety (proven in R7): pre-tile joint renorm brings all tile inputs
// <= 2 (overflow impossible); two-stage power-of-2 factors; post-tile renorm
// exponent clamped; all state commits guarded by the active window.
// This round: __launch_bounds__(128,1) to unlock registers, 8 rows/superstep
// (95 supersteps, 191 total hops), branch-free lane-0 merge (SEL not BSSY).

#define TLEN  512
#define BATCH 32
#define NTH   128
#define ROWS  8
#define RB    (TLEN / ROWS)      // 64 row-blocks
#define WSUP  (RB + 31)          // 95 supersteps per warp
#define SENT  0x7fffffff

__device__ __forceinline__ float pow2i(int e) {   // e in [-126,126]
    return __int_as_float((e + 127) << 23);
}

__global__ __launch_bounds__(NTH, 1) void softdtw_kernel(const float* __restrict__ x,
                                                         const float* __restrict__ y,
                                                         float* __restrict__ out) {
    __shared__ float cs[TLEN];          // c_i = 2^{-ds'[i]}
    __shared__ float redsum[4];
    __shared__ int   ring[3][192][12];  // [boundary][slot][0..7 W raw, 8 = k tag/flag]

    const int q    = threadIdx.x;
    const int lane = q & 31;
    const int w    = q >> 5;
    const int b    = blockIdx.x;

    // ---- prologue -----------------------------------------------------------
    const float L2E = 1.4426950408889634f;
    float4 xv = ((const float4*)(x + b * TLEN))[q];
    float4 yv = ((const float4*)(y + b * TLEN))[q];
    float e0 = (xv.x - yv.x) * (xv.x - yv.x) * L2E;
    float e1 = (xv.y - yv.y) * (xv.y - yv.y) * L2E;
    float e2 = (xv.z - yv.z) * (xv.z - yv.z) * L2E;
    float e3 = (xv.w - yv.w) * (xv.w - yv.w) * L2E;
    cs[4*q + 0] = exp2f(-e0);
    cs[4*q + 1] = exp2f(-e1);
    cs[4*q + 2] = exp2f(-e2);
    cs[4*q + 3] = exp2f(-e3);
    float mysum = (e0 + e1) + (e2 + e3);
    #pragma unroll
    for (int o = 16; o; o >>= 1) mysum += __shfl_xor_sync(0xffffffffu, mysum, o);
    if (lane == 0) redsum[w] = mysum;
    for (int s = q; s < 3 * 192; s += NTH) ring[s / 192][s % 192][8] = SENT;
    __syncthreads();
    const float P = (redsum[0] + redsum[1]) + (redsum[2] + redsum[3]);

    // ---- state --------------------------------------------------------------
    float u0 = 0.f, u1 = 0.f, u2 = 0.f, u3 = 0.f;   // up-carries (cols), frame k
    float nb[ROWS];                                  // published boundary, frame kold
    #pragma unroll
    for (int r = 0; r < ROWS; ++r) nb[r] = 0.f;
    float dgW = (q == 0) ? 1.0f : 0.0f;             // diag input for next row0
    int   k = 0, kold = 0;

    const int t0 = w << 5;
    for (int ts = 0; ts < WSUP; ++ts) {
        const int t = t0 + ts;

        // ---- receive left boundary (8 rows) + producer frame ----
        float lr[ROWS];
        #pragma unroll
        for (int r = 0; r < ROWS; ++r) lr[r] = __shfl_up_sync(0xffffffffu, nb[r], 1);
        int kp = __shfl_up_sync(0xffffffffu, kold, 1);

        if (w > 0 && ts < RB) {
            // warp-uniform spin on producer slot, then branch-free lane-0 merge
            unsigned fa = (unsigned)__cvta_generic_to_shared(&ring[w - 1][t - 1][8]);
            int kv;
            do {
                asm volatile("ld.acquire.cta.shared.b32 %0, [%1];" : "=r"(kv) : "r"(fa) : "memory");
            } while (kv == SENT);
            #pragma unroll
            for (int r = 0; r < ROWS; ++r) {
                float rv = __int_as_float(ring[w - 1][t - 1][r]);   // broadcast LDS
                lr[r] = (lane == 0) ? rv : lr[r];
            }
            kp = (lane == 0) ? kv : kp;
        } else {
            #pragma unroll
            for (int r = 0; r < ROWS; ++r) lr[r] = (lane == 0) ? 0.0f : lr[r];
            kp = (lane == 0) ? k : kp;
        }

        const bool act = (unsigned)(ts - lane) < (unsigned)RB;

        // ---- pre-tile joint renorm: bring all tile inputs to <= 2 ----
        const int dk = kp - k;
        float mlx = lr[0];
        #pragma unroll
        for (int r = 1; r < ROWS; ++r) mlx = fmaxf(mlx, lr[r]);
        const int el = ((__float_as_int(mlx) >> 23) - 127) + dk;
        const int s  = el > 0 ? el : 0;
        const int kt = k + s;                         // tile frame
        const int hl = dk - s;                        // shift for l into tile frame
        {
            int h1 = hl < -126 ? -126 : (hl > 126 ? 126 : hl);
            int h2 = hl - h1;
            h2 = h2 < -126 ? -126 : (h2 > 126 ? 126 : h2);
            const float fa1 = pow2i(h1), fa2 = pow2i(h2);
            #pragma unroll
            for (int r = 0; r < ROWS; ++r) lr[r] = lr[r] * fa1 * fa2;
        }
        int s1 = s > 126 ? 126 : s;
        int s2 = s - s1; s2 = s2 > 126 ? 126 : s2;
        const float uf1 = pow2i(-s1), uf2 = pow2i(-s2);
        float p0 = u0 * uf1 * uf2, p1 = u1 * uf1 * uf2;
        float p2 = u2 * uf1 * uf2, p3 = u3 * uf1 * uf2;
        float dl = dgW * uf1 * uf2;

        // ---- row costs for this superstep's 8 rows ----
        int ridx = ts - lane;
        ridx = ridx < 0 ? 0 : (ridx > RB - 1 ? RB - 1 : ridx);
        float c8[ROWS];
        {
            const float4 ca = *(const float4*)&cs[ROWS * ridx];
            const float4 cb = *(const float4*)&cs[ROWS * ridx + 4];
            c8[0] = ca.x; c8[1] = ca.y; c8[2] = ca.z; c8[3] = ca.w;
            c8[4] = cb.x; c8[5] = cb.y; c8[6] = cb.z; c8[7] = cb.w;
        }

        // ---- 32 cells: W = (up + dg) + c * left ----
        float tnb[ROWS];
        #pragma unroll
        for (int r = 0; r < ROWS; ++r) {
            const float cr = c8[r];
            const float t0c = fmaf(cr, lr[r], p0 + dl);
            const float t1c = fmaf(cr, t0c,   p1 + p0);
            const float t2c = fmaf(cr, t1c,   p2 + p1);
            const float t3c = fmaf(cr, t2c,   p3 + p2);
            tnb[r] = t3c;
            dl = lr[r];
            p0 = t0c; p1 = t1c; p2 = t2c; p3 = t3c;
        }

        // ---- post-tile renorm (tile growth bounded: values <= ~2^15) ----
        const float mx = fmaxf(fmaxf(p0, p1), fmaxf(p2, p3));
        int e = (__float_as_int(mx) >> 23) - 127;
        e = e < -126 ? -126 : (e > 126 ? 126 : e);
        if (mx == 0.0f) e = 0;
        const float g = pow2i(-e);

        // ---- commit (active window only) ----
        if (act) {
            u0 = p0 * g; u1 = p1 * g; u2 = p2 * g; u3 = p3 * g;
            dgW = lr[ROWS - 1] * g;
            k = kt + e;
            #pragma unroll
            for (int r = 0; r < ROWS; ++r) nb[r] = tnb[r];   // tile frame kt
            kold = kt;
        }

        if (lane == 31 && w < 3) {
            #pragma unroll
            for (int r = 0; r < ROWS; ++r) ring[w][t][r] = __float_as_int(nb[r]);
            unsigned fa = (unsigned)__cvta_generic_to_shared(&ring[w][t][8]);
            asm volatile("st.release.cta.shared.b32 [%0], %1;" :: "r"(fa), "r"(kold) : "memory");
        }
    }

    if (q == NTH - 1) {
        // R(T,T)*log2e = P - k - log2(W_raw); unscale by ln2; mean over batches.
        float Rl2 = P - (float)k - __log2f(u3);
        atomicAdd(out, Rl2 * 0.6931471805599453f * (1.0f / BATCH));
    }
}

extern "C" void kernel_launch(void* const* d_in, const int* in_sizes, int n_in,
                              void* d_out, int out_size) {
    const float* x = (const float*)d_in[0];
    const float* y = (const float*)d_in[1];
    cudaMemsetAsync(d_out, 0, sizeof(float));
    softdtw_kernel<<<BATCH, NTH>>>(x, y, (float*)d_out);
}